// round 1
// baseline (speedup 1.0000x reference)
#include <cuda_runtime.h>
#include <math.h>

// Problem constants
#define NBATCH 4
#define CCH    16
#define DIM    32
#define OD     31            // DIM-1
#define PVOL   (31*31*31)    // 29791 outputs per batch
#define MROWS  (NBATCH*PVOL) // 119164
#define D1     512
#define KK     128           // C * 2^3
#define BM     64
#define BN     64
#define LDA    65            // padded smem leading dim

__global__ __launch_bounds__(256)
void gk_kernel(const float* __restrict__ x, const float* __restrict__ w,
               float* __restrict__ out) {
    extern __shared__ float sm[];
    float* sA  = sm;                 // [KK][LDA]  y tile, k-major
    float* sB  = sm + KK * LDA;      // [KK][LDA]  w tile, k-major
    float* ysq = sm + 2 * KK * LDA;  // [BM]
    float* wsq = ysq + BM;           // [BN]

    const int tid  = threadIdx.x;
    const int row0 = blockIdx.x * BM;
    const int col0 = blockIdx.y * BN;

    // ---------------- gather A (patches) ----------------
    // thread owns row m = tid&63, k = it*4 + (tid>>6); lanes are consecutive m
    // for a fixed k -> consecutive p -> coalesced global reads of x.
    {
        const int m     = tid & 63;
        const int kbase = tid >> 6;      // 0..3
        const int row   = row0 + m;
        if (row < MROWS) {
            const int n   = row / PVOL;
            const int p   = row - n * PVOL;
            const int d   = p / 961;
            const int rem = p - d * 961;
            const int h   = rem / 31;
            const int wx  = rem - h * 31;
            const long xoff = (long)n * (CCH * 32768) + d * 1024 + h * 32 + wx;
            // k = it*4 + kbase : low 2 bits (kh,kw) fixed per thread
            const int kh = (kbase >> 1) & 1;
            const int kw = kbase & 1;
            const long base = xoff + kh * 32 + kw;
            #pragma unroll
            for (int it = 0; it < 32; ++it) {
                const int k  = it * 4 + kbase;
                const int c  = it >> 1;       // k>>3
                const int kd = it & 1;        // (k>>2)&1
                sA[k * LDA + m] = x[base + (long)c * 32768 + kd * 1024];
            }
        } else {
            #pragma unroll
            for (int it = 0; it < 32; ++it)
                sA[(it * 4 + kbase) * LDA + m] = 0.0f;
        }
    }
    // ---------------- gather B (w tile) ----------------
    // thread owns k = tid&127, nn = it*2 + (tid>>7); lanes consecutive k for
    // fixed nn -> coalesced reads of 512B w rows; smem stores stride-65 -> cf.
    {
        const int k  = tid & 127;
        const int nb = tid >> 7;         // 0..1
        #pragma unroll
        for (int it = 0; it < 32; ++it) {
            const int nn = it * 2 + nb;
            sB[k * LDA + nn] = w[(col0 + nn) * KK + k];
        }
    }
    __syncthreads();

    // ---------------- per-row / per-col squared norms ----------------
    if (tid < BM) {
        float s = 0.0f;
        #pragma unroll 8
        for (int k = 0; k < KK; ++k) { float v = sA[k * LDA + tid]; s = fmaf(v, v, s); }
        ysq[tid] = s;
    } else if (tid >= 192) {
        const int nn = tid - 192;
        float s = 0.0f;
        #pragma unroll 8
        for (int k = 0; k < KK; ++k) { float v = sB[k * LDA + nn]; s = fmaf(v, v, s); }
        wsq[nn] = s;
    }
    __syncthreads();

    // ---------------- main GEMM: 4x4 micro-tile per thread ----------------
    const int tx = tid & 15;   // row group
    const int ty = tid >> 4;   // col group
    const int tm = tx * 4;
    const int tn = ty * 4;

    float acc[4][4] = {};
    #pragma unroll 4
    for (int k = 0; k < KK; ++k) {
        float a0 = sA[k * LDA + tm + 0];
        float a1 = sA[k * LDA + tm + 1];
        float a2 = sA[k * LDA + tm + 2];
        float a3 = sA[k * LDA + tm + 3];
        float b0 = sB[k * LDA + tn + 0];
        float b1 = sB[k * LDA + tn + 1];
        float b2 = sB[k * LDA + tn + 2];
        float b3 = sB[k * LDA + tn + 3];
        acc[0][0] = fmaf(a0, b0, acc[0][0]);
        acc[0][1] = fmaf(a0, b1, acc[0][1]);
        acc[0][2] = fmaf(a0, b2, acc[0][2]);
        acc[0][3] = fmaf(a0, b3, acc[0][3]);
        acc[1][0] = fmaf(a1, b0, acc[1][0]);
        acc[1][1] = fmaf(a1, b1, acc[1][1]);
        acc[1][2] = fmaf(a1, b2, acc[1][2]);
        acc[1][3] = fmaf(a1, b3, acc[1][3]);
        acc[2][0] = fmaf(a2, b0, acc[2][0]);
        acc[2][1] = fmaf(a2, b1, acc[2][1]);
        acc[2][2] = fmaf(a2, b2, acc[2][2]);
        acc[2][3] = fmaf(a2, b3, acc[2][3]);
        acc[3][0] = fmaf(a3, b0, acc[3][0]);
        acc[3][1] = fmaf(a3, b1, acc[3][1]);
        acc[3][2] = fmaf(a3, b2, acc[3][2]);
        acc[3][3] = fmaf(a3, b3, acc[3][3]);
    }

    float ys[4], ws[4];
    #pragma unroll
    for (int i = 0; i < 4; ++i) ys[i] = ysq[tm + i];
    #pragma unroll
    for (int j = 0; j < 4; ++j) ws[j] = wsq[tn + j];

    float val[4][4];
    #pragma unroll
    for (int i = 0; i < 4; ++i)
        #pragma unroll
        for (int j = 0; j < 4; ++j)
            val[i][j] = expf(fmaf(2.0f, acc[i][j], -ys[i] - ws[j]));

    // ---------------- stage + coalesced store ----------------
    __syncthreads();                  // done reading sA/sB
    float* st = sA;                   // reuse as [BN][LDA] (col-major stage)
    #pragma unroll
    for (int j = 0; j < 4; ++j)
        #pragma unroll
        for (int i = 0; i < 4; ++i)
            st[(tn + j) * LDA + (tm + i)] = val[i][j];
    __syncthreads();

    #pragma unroll
    for (int e = tid; e < BM * BN; e += 256) {
        const int col = e >> 6;
        const int m   = e & 63;
        const int row = row0 + m;
        if (row < MROWS) {
            const int n = row / PVOL;
            const int p = row - n * PVOL;
            out[(long)(n * D1 + col0 + col) * PVOL + p] = st[col * LDA + m];
        }
    }
}

extern "C" void kernel_launch(void* const* d_in, const int* in_sizes, int n_in,
                              void* d_out, int out_size) {
    const float* x = (const float*)d_in[0];
    const float* w = (const float*)d_in[1];
    float* out = (float*)d_out;

    const int smem_bytes = (2 * KK * LDA + BM + BN) * (int)sizeof(float); // 67,072
    cudaFuncSetAttribute(gk_kernel, cudaFuncAttributeMaxDynamicSharedMemorySize,
                         smem_bytes);

    dim3 grid((MROWS + BM - 1) / BM, D1 / BN);  // (1862, 8)
    gk_kernel<<<grid, 256, smem_bytes>>>(x, w, out);
}

// round 2
// speedup vs baseline: 1.2145x; 1.2145x over previous
#include <cuda_runtime.h>

// Problem constants
#define NBATCH 4
#define PVOL   29791          // 31^3
#define MROWS  119164         // 4 * 31^3
#define D1     512
#define KK     128            // C(16) * 2^3
#define BM     128
#define BN     128
#define LDA    132            // padded smem leading dims (16B-aligned rows)
#define LDB    132

__device__ __forceinline__ unsigned long long pack2(float lo, float hi) {
    unsigned long long r;
    asm("mov.b64 %0, {%1, %2};" : "=l"(r) : "f"(lo), "f"(hi));
    return r;
}
__device__ __forceinline__ void unpack2(unsigned long long v, float& lo, float& hi) {
    asm("mov.b64 {%0, %1}, %2;" : "=f"(lo), "=f"(hi) : "l"(v));
}
__device__ __forceinline__ void ffma2(unsigned long long& acc,
                                      unsigned long long a, unsigned long long b) {
    asm("fma.rn.f32x2 %0, %1, %2, %0;" : "+l"(acc) : "l"(a), "l"(b));
}

__global__ __launch_bounds__(256, 1)
void gk_kernel(const float* __restrict__ x, const float* __restrict__ w,
               float* __restrict__ out) {
    extern __shared__ float sm[];
    float* sA  = sm;                  // [KK][LDA] patch tile, k-major
    float* sB  = sm + KK * LDA;       // [KK][LDB] w tile, k-major
    float* ysq = sm + 2 * KK * LDA;   // [BM]
    float* wsq = ysq + BM;            // [BN]

    const int tid  = threadIdx.x;
    const int row0 = blockIdx.x * BM;
    const int col0 = blockIdx.y * BN;

    // ---------------- gather A: 2x2x2xC patches, k-major, coalesced in m ----
    {
        const int m  = tid & 127;
        const int kw = tid >> 7;          // 0..1 (innermost patch offset)
        const int row = row0 + m;
        if (row < MROWS) {
            const int n   = row / PVOL;
            const int p   = row - n * PVOL;
            const int d   = p / 961;
            const int rem = p - d * 961;
            const int h   = rem / 31;
            const int wx  = rem - h * 31;
            const long base = (long)n * 524288 + d * 1024 + h * 32 + wx + kw;
            #pragma unroll 8
            for (int it = 0; it < 64; ++it) {
                const int c  = it >> 2;
                const int kd = (it >> 1) & 1;
                const int kh = it & 1;
                const int k  = it * 2 + kw;    // k = c*8 + kd*4 + kh*2 + kw
                sA[k * LDA + m] = x[base + (long)c * 32768 + kd * 1024 + kh * 32];
            }
        } else {
            #pragma unroll 8
            for (int it = 0; it < 64; ++it)
                sA[(it * 2 + kw) * LDA + m] = 0.0f;
        }
    }
    // ---------------- gather B: coalesced 512B rows of w ---------------------
    {
        const int k  = tid & 127;
        const int nb = tid >> 7;
        #pragma unroll 8
        for (int it = 0; it < 64; ++it) {
            const int nn = it * 2 + nb;
            sB[k * LDB + nn] = w[(col0 + nn) * KK + k];
        }
    }
    __syncthreads();

    // ---------------- squared norms --------------------------------------
    if (tid < BM) {
        float s = 0.0f;
        #pragma unroll 8
        for (int k = 0; k < KK; ++k) { float v = sA[k * LDA + tid]; s = fmaf(v, v, s); }
        ysq[tid] = s;
    } else {
        const int nn = tid - 128;
        float s = 0.0f;
        #pragma unroll 8
        for (int k = 0; k < KK; ++k) { float v = sB[k * LDB + nn]; s = fmaf(v, v, s); }
        wsq[nn] = s;
    }
    __syncthreads();

    // ---------------- main GEMM: 8x8 micro-tile, packed f32x2 FMAs ---------
    const int tx = tid & 15;
    const int ty = tid >> 4;
    const int tm = tx * 8;
    const int tn = ty * 8;

    unsigned long long acc[4][8];
    #pragma unroll
    for (int i = 0; i < 4; ++i)
        #pragma unroll
        for (int j = 0; j < 8; ++j) acc[i][j] = 0ull;

    #pragma unroll 4
    for (int k = 0; k < KK; ++k) {
        const float4 a0 = *(const float4*)&sA[k * LDA + tm];
        const float4 a1 = *(const float4*)&sA[k * LDA + tm + 4];
        const float4 b0 = *(const float4*)&sB[k * LDB + tn];
        const float4 b1 = *(const float4*)&sB[k * LDB + tn + 4];

        unsigned long long A[4];
        A[0] = pack2(a0.x, a0.y);
        A[1] = pack2(a0.z, a0.w);
        A[2] = pack2(a1.x, a1.y);
        A[3] = pack2(a1.z, a1.w);

        unsigned long long B[8];
        B[0] = pack2(b0.x, b0.x);
        B[1] = pack2(b0.y, b0.y);
        B[2] = pack2(b0.z, b0.z);
        B[3] = pack2(b0.w, b0.w);
        B[4] = pack2(b1.x, b1.x);
        B[5] = pack2(b1.y, b1.y);
        B[6] = pack2(b1.z, b1.z);
        B[7] = pack2(b1.w, b1.w);

        #pragma unroll
        for (int i = 0; i < 4; ++i)
            #pragma unroll
            for (int j = 0; j < 8; ++j)
                ffma2(acc[i][j], A[i], B[j]);
    }

    float ys[8], ws[8];
    #pragma unroll
    for (int i = 0; i < 8; ++i) ys[i] = ysq[tm + i];
    #pragma unroll
    for (int j = 0; j < 8; ++j) ws[j] = wsq[tn + j];

    __syncthreads();                  // sA/sB reads done; reuse sA as stage

    // ---------------- epilogue: exp + stage (vectorized f32x2 stores) ------
    float* st = sA;                   // [BN][LDA] column-major stage
    #pragma unroll
    for (int i = 0; i < 4; ++i) {
        #pragma unroll
        for (int j = 0; j < 8; ++j) {
            float v0, v1;
            unpack2(acc[i][j], v0, v1);
            const float c0 = ys[2 * i]     + ws[j];
            const float c1 = ys[2 * i + 1] + ws[j];
            float e0 = __expf(fmaf(2.0f, v0, -c0));
            float e1 = __expf(fmaf(2.0f, v1, -c1));
            *(float2*)&st[(tn + j) * LDA + tm + 2 * i] = make_float2(e0, e1);
        }
    }
    __syncthreads();

    // ---------------- coalesced global stores -------------------------------
    #pragma unroll 4
    for (int l = 0; l < 64; ++l) {
        const int e   = tid + l * 256;
        const int col = e >> 7;           // 0..127
        const int m   = e & 127;
        const int row = row0 + m;
        if (row < MROWS) {
            const int n = row / PVOL;
            const int p = row - n * PVOL;
            out[(long)(n * D1 + col0 + col) * PVOL + p] = st[col * LDA + m];
        }
    }
}

extern "C" void kernel_launch(void* const* d_in, const int* in_sizes, int n_in,
                              void* d_out, int out_size) {
    const float* x = (const float*)d_in[0];
    const float* w = (const float*)d_in[1];
    float* out = (float*)d_out;

    const int smem_bytes = (2 * KK * LDA + BM + BN) * (int)sizeof(float); // 136,192
    cudaFuncSetAttribute(gk_kernel, cudaFuncAttributeMaxDynamicSharedMemorySize,
                         smem_bytes);

    dim3 grid((MROWS + BM - 1) / BM, D1 / BN);  // (931, 4)
    gk_kernel<<<grid, 256, smem_bytes>>>(x, w, out);
}